// round 1
// baseline (speedup 1.0000x reference)
#include <cuda_runtime.h>

// DiffKS: fused time-varying FIR (order 6) + time-varying all-pole IIR (order 2).
//   x[t]  = y[t] + sum_{k=1..6} Ae[b,t,k-1] * y[t-k]          (zero-padded history)
//   out[t]= x[t] - sum_{k=1..2} Al[b,t,k-1] * out[t-k]        (zero initial state)
//
// Parallelization: per-(batch, chunk) thread. IIR state is contractive
// (|a| < 0.25 -> worst-case per-step factor ~0.64), so a 96-sample warmup from
// zero state reconstructs the true state to ~1e-19. FIR history is exact
// (loaded directly from the input y). Chunk 0 is bit-exact.

#define BATCH 48
#define TLEN  88200
#define NE    6
#define NL    2
#define CHUNK 336                 // multiple of 4 (float4 alignment)
#define WARM  96                  // multiple of 4
#define NCH   ((TLEN + CHUNK - 1) / CHUNK)   // 263
#define NTHREADS (BATCH * NCH)               // 12624

__global__ void __launch_bounds__(64)
diffks_kernel(const float* __restrict__ y,
              const float* __restrict__ Ae,
              const float* __restrict__ Al,
              float* __restrict__ out)
{
    int gid = blockIdx.x * blockDim.x + threadIdx.x;
    if (gid >= NTHREADS) return;

    int b = gid / NCH;
    int c = gid - b * NCH;

    int start  = c * CHUNK;
    int wstart = start - WARM;
    if (wstart < 0) wstart = 0;
    int tend = min(start + CHUNK, TLEN);   // TLEN%4==0 and start+CHUNK%4==0 -> tend%4==0

    const float* yb  = y   + (size_t)b * TLEN;
    const float* aeb = Ae  + (size_t)b * TLEN * NE;
    const float* alb = Al  + (size_t)b * TLEN * NL;
    float*       ob  = out + (size_t)b * TLEN;

    // FIR history window: h_k = y[t-1-k], exact (y is an input).
    float h0 = (wstart - 1 >= 0) ? yb[wstart - 1] : 0.f;
    float h1 = (wstart - 2 >= 0) ? yb[wstart - 2] : 0.f;
    float h2 = (wstart - 3 >= 0) ? yb[wstart - 3] : 0.f;
    float h3 = (wstart - 4 >= 0) ? yb[wstart - 4] : 0.f;
    float h4 = (wstart - 5 >= 0) ? yb[wstart - 5] : 0.f;
    float h5 = (wstart - 6 >= 0) ? yb[wstart - 6] : 0.f;

    // IIR state: zero at wstart (exact for chunk 0; warmup-converged otherwise).
    float s1 = 0.f, s2 = 0.f;

    for (int t = wstart; t < tend; t += 4) {
        float4 y4 = *reinterpret_cast<const float4*>(yb + t);

        const float4* ep = reinterpret_cast<const float4*>(aeb + (size_t)t * NE);
        float4 e0 = ep[0], e1 = ep[1], e2 = ep[2];
        float4 e3 = ep[3], e4 = ep[4], e5 = ep[5];

        const float4* lp = reinterpret_cast<const float4*>(alb + (size_t)t * NL);
        float4 l0 = lp[0], l1 = lp[1];

        float4 o4;
        float x, yo;

        // sample t+0 : Ae idx 0..5 = e0.xyzw, e1.xy ; Al = l0.xy
        x  = y4.x + e0.x*h0 + e0.y*h1 + e0.z*h2 + e0.w*h3 + e1.x*h4 + e1.y*h5;
        yo = x - l0.x*s1 - l0.y*s2;
        s2 = s1; s1 = yo; o4.x = yo;
        h5 = h4; h4 = h3; h3 = h2; h2 = h1; h1 = h0; h0 = y4.x;

        // sample t+1 : Ae idx 6..11 = e1.zw, e2.xyzw ; Al = l0.zw
        x  = y4.y + e1.z*h0 + e1.w*h1 + e2.x*h2 + e2.y*h3 + e2.z*h4 + e2.w*h5;
        yo = x - l0.z*s1 - l0.w*s2;
        s2 = s1; s1 = yo; o4.y = yo;
        h5 = h4; h4 = h3; h3 = h2; h2 = h1; h1 = h0; h0 = y4.y;

        // sample t+2 : Ae idx 12..17 = e3.xyzw, e4.xy ; Al = l1.xy
        x  = y4.z + e3.x*h0 + e3.y*h1 + e3.z*h2 + e3.w*h3 + e4.x*h4 + e4.y*h5;
        yo = x - l1.x*s1 - l1.y*s2;
        s2 = s1; s1 = yo; o4.z = yo;
        h5 = h4; h4 = h3; h3 = h2; h2 = h1; h1 = h0; h0 = y4.z;

        // sample t+3 : Ae idx 18..23 = e4.zw, e5.xyzw ; Al = l1.zw
        x  = y4.w + e4.z*h0 + e4.w*h1 + e5.x*h2 + e5.y*h3 + e5.z*h4 + e5.w*h5;
        yo = x - l1.z*s1 - l1.w*s2;
        s2 = s1; s1 = yo; o4.w = yo;
        h5 = h4; h4 = h3; h3 = h2; h2 = h1; h1 = h0; h0 = y4.w;

        if (t >= start) {
            *reinterpret_cast<float4*>(ob + t) = o4;
        }
    }
}

extern "C" void kernel_launch(void* const* d_in, const int* in_sizes, int n_in,
                              void* d_out, int out_size)
{
    const float* y  = (const float*)d_in[0];
    const float* Ae = (const float*)d_in[1];
    const float* Al = (const float*)d_in[2];
    float* out = (float*)d_out;

    int blocks = (NTHREADS + 63) / 64;
    diffks_kernel<<<blocks, 64>>>(y, Ae, Al, out);
}

// round 2
// speedup vs baseline: 2.5353x; 2.5353x over previous
#include <cuda_runtime.h>

// DiffKS: fused time-varying FIR (order 6) + time-varying all-pole IIR (order 2).
//   x[t]  = y[t] + sum_{k=1..6} Ae[b,t,k-1] * y[t-k]          (zero-padded history)
//   out[t]= x[t] - sum_{k=1..2} Al[b,t,k-1] * out[t-k]        (zero initial state)
//
// Per-(batch,chunk) thread with IIR warmup from zero state. |a_loop| <= 0.25
// -> worst-case per-step contraction 0.64, so WARM=64 gives <4e-13 state error.
// FIR history is exact (read from input y). Chunk 0 is bit-exact.
//
// R1 lesson: latency-bound (occ 3.9%, DRAM 15.7%). This version: 3x more
// threads (CHUNK 336->112) + explicit 1-deep load double-buffering so next
// iteration's 9 loads are in flight during current iteration's FMA chain.

#define BATCH 48
#define TLEN  88200
#define NE    6
#define NL    2
#define CHUNK 112                 // multiple of 4
#define WARM  64                  // multiple of 4
#define NCH   ((TLEN + CHUNK - 1) / CHUNK)   // 788
#define NTHREADS (BATCH * NCH)               // 37824
#define TPB   128

__global__ void __launch_bounds__(TPB)
diffks_kernel(const float* __restrict__ y,
              const float* __restrict__ Ae,
              const float* __restrict__ Al,
              float* __restrict__ out)
{
    int gid = blockIdx.x * blockDim.x + threadIdx.x;
    if (gid >= NTHREADS) return;

    int b = gid / NCH;
    int c = gid - b * NCH;

    int start  = c * CHUNK;
    int wstart = start - WARM;
    if (wstart < 0) wstart = 0;
    int tend = min(start + CHUNK, TLEN);   // multiples of 4 throughout

    const float* yb  = y   + (size_t)b * TLEN;
    const float* aeb = Ae  + (size_t)b * TLEN * NE;
    const float* alb = Al  + (size_t)b * TLEN * NL;
    float*       ob  = out + (size_t)b * TLEN;

    // FIR history window: h_k = y[t-1-k], exact.
    float h0 = (wstart - 1 >= 0) ? yb[wstart - 1] : 0.f;
    float h1 = (wstart - 2 >= 0) ? yb[wstart - 2] : 0.f;
    float h2 = (wstart - 3 >= 0) ? yb[wstart - 3] : 0.f;
    float h3 = (wstart - 4 >= 0) ? yb[wstart - 4] : 0.f;
    float h4 = (wstart - 5 >= 0) ? yb[wstart - 5] : 0.f;
    float h5 = (wstart - 6 >= 0) ? yb[wstart - 6] : 0.f;

    float s1 = 0.f, s2 = 0.f;

    // ---- prologue: load iteration 0 ----
    float4 y4, e0, e1, e2, e3, e4, e5, l0, l1;
    {
        int t = wstart;
        y4 = *reinterpret_cast<const float4*>(yb + t);
        const float4* ep = reinterpret_cast<const float4*>(aeb + (size_t)t * NE);
        e0 = ep[0]; e1 = ep[1]; e2 = ep[2]; e3 = ep[3]; e4 = ep[4]; e5 = ep[5];
        const float4* lp = reinterpret_cast<const float4*>(alb + (size_t)t * NL);
        l0 = lp[0]; l1 = lp[1];
    }

    for (int t = wstart; t < tend; t += 4) {
        // ---- prefetch iteration t+4 (clamped: re-reads current on last iter, L1 hit) ----
        int tn = t + 4;
        if (tn >= tend) tn = t;
        float4 ny4 = *reinterpret_cast<const float4*>(yb + tn);
        const float4* nep = reinterpret_cast<const float4*>(aeb + (size_t)tn * NE);
        float4 ne0 = nep[0], ne1 = nep[1], ne2 = nep[2];
        float4 ne3 = nep[3], ne4 = nep[4], ne5 = nep[5];
        const float4* nlp = reinterpret_cast<const float4*>(alb + (size_t)tn * NL);
        float4 nl0 = nlp[0], nl1 = nlp[1];

        // ---- compute current 4 samples ----
        float4 o4;
        float x, yo;

        // t+0 : Ae = e0.xyzw, e1.xy ; Al = l0.xy
        x  = y4.x + e0.x*h0 + e0.y*h1 + e0.z*h2 + e0.w*h3 + e1.x*h4 + e1.y*h5;
        yo = x - l0.x*s1 - l0.y*s2;
        s2 = s1; s1 = yo; o4.x = yo;
        h5 = h4; h4 = h3; h3 = h2; h2 = h1; h1 = h0; h0 = y4.x;

        // t+1 : Ae = e1.zw, e2.xyzw ; Al = l0.zw
        x  = y4.y + e1.z*h0 + e1.w*h1 + e2.x*h2 + e2.y*h3 + e2.z*h4 + e2.w*h5;
        yo = x - l0.z*s1 - l0.w*s2;
        s2 = s1; s1 = yo; o4.y = yo;
        h5 = h4; h4 = h3; h3 = h2; h2 = h1; h1 = h0; h0 = y4.y;

        // t+2 : Ae = e3.xyzw, e4.xy ; Al = l1.xy
        x  = y4.z + e3.x*h0 + e3.y*h1 + e3.z*h2 + e3.w*h3 + e4.x*h4 + e4.y*h5;
        yo = x - l1.x*s1 - l1.y*s2;
        s2 = s1; s1 = yo; o4.z = yo;
        h5 = h4; h4 = h3; h3 = h2; h2 = h1; h1 = h0; h0 = y4.z;

        // t+3 : Ae = e4.zw, e5.xyzw ; Al = l1.zw
        x  = y4.w + e4.z*h0 + e4.w*h1 + e5.x*h2 + e5.y*h3 + e5.z*h4 + e5.w*h5;
        yo = x - l1.z*s1 - l1.w*s2;
        s2 = s1; s1 = yo; o4.w = yo;
        h5 = h4; h4 = h3; h3 = h2; h2 = h1; h1 = h0; h0 = y4.w;

        if (t >= start) {
            *reinterpret_cast<float4*>(ob + t) = o4;
        }

        // ---- rotate buffers ----
        y4 = ny4;
        e0 = ne0; e1 = ne1; e2 = ne2; e3 = ne3; e4 = ne4; e5 = ne5;
        l0 = nl0; l1 = nl1;
    }
}

extern "C" void kernel_launch(void* const* d_in, const int* in_sizes, int n_in,
                              void* d_out, int out_size)
{
    const float* y  = (const float*)d_in[0];
    const float* Ae = (const float*)d_in[1];
    const float* Al = (const float*)d_in[2];
    float* out = (float*)d_out;

    int blocks = (NTHREADS + TPB - 1) / TPB;
    diffks_kernel<<<blocks, TPB>>>(y, Ae, Al, out);
}